// round 2
// baseline (speedup 1.0000x reference)
#include <cuda_runtime.h>

#define BB 128
#define TT 1024
#define DD 1024
#define HH 1024
#define NG 4096   // 4*H
#define NCTA 128  // persistent phase-2 CTAs (one wave; 148 SMs)

typedef unsigned long long ull;

// Scratch: x_proj[t][b][4H] fp32, split into two 1 GB halves (t<512 / t>=512)
__device__ float g_xp0[(size_t)512 * BB * NG];
__device__ float g_xp1[(size_t)512 * BB * NG];
__device__ float g_h[2][BB * HH];   // ping-pong hidden state
__device__ float g_c[BB * HH];      // cell state (in-place per element)
__device__ unsigned g_bar;          // monotonic grid-barrier counter

// ---- packed f32x2 helpers (sm_10x dual-lane fp32) -------------------------
__device__ __forceinline__ ull fma2(ull a, ull b, ull c) {
    ull d;
    asm("fma.rn.f32x2 %0, %1, %2, %3;" : "=l"(d) : "l"(a), "l"(b), "l"(c));
    return d;
}
__device__ __forceinline__ ull pack2(float lo, float hi) {
    ull d;
    asm("mov.b64 %0, {%1, %2};" : "=l"(d) : "f"(lo), "f"(hi));
    return d;
}
__device__ __forceinline__ float2 unpack2(ull v) {
    float2 r;
    asm("mov.b64 {%0, %1}, %2;" : "=f"(r.x), "=f"(r.y) : "l"(v));
    return r;
}
__device__ __forceinline__ unsigned ld_acq(const unsigned* p) {
    unsigned v;
    asm volatile("ld.global.acquire.gpu.u32 %0, [%1];" : "=r"(v) : "l"(p));
    return v;
}

// ---------------------------------------------------------------------------
// Zero h0, c0, barrier counter (re-runs every replay -> deterministic)
// ---------------------------------------------------------------------------
__global__ void init_kernel() {
    int i = blockIdx.x * blockDim.x + threadIdx.x;
    if (i < BB * HH) {
        g_h[0][i] = 0.f;
        g_c[i] = 0.f;
    }
    if (i == 0) g_bar = 0u;
}

// ---------------------------------------------------------------------------
// Phase 1: x_proj[t][b][g] = sum_d x[b][t][d] * Wi[d][g] + bias[g]
// A = x viewed as [B*T, D]. C tile 128x128, 256 threads, 8x8 per thread
// (accumulated as 8 x 4 f32x2), BK=16.
// ---------------------------------------------------------------------------
__global__ __launch_bounds__(256) void xproj_kernel(
    const float* __restrict__ x,
    const float* __restrict__ Wii, const float* __restrict__ Wif,
    const float* __restrict__ Wig, const float* __restrict__ Wio,
    const float* __restrict__ b_i, const float* __restrict__ b_f,
    const float* __restrict__ b_g, const float* __restrict__ b_o)
{
    __shared__ float As[16][128];   // As[k][m]
    __shared__ float Bs[16][128];   // Bs[k][n]

    const int tid = threadIdx.x;
    const int n0 = blockIdx.x * 128;            // global gate col base
    const size_t m0 = (size_t)blockIdx.y * 128; // row base over B*T

    const int gate = n0 >> 10;
    const int col0 = n0 & 1023;
    const float* __restrict__ W =
        (gate == 0) ? Wii : (gate == 1) ? Wif : (gate == 2) ? Wig : Wio;
    const float* __restrict__ bias =
        (gate == 0) ? b_i : (gate == 1) ? b_f : (gate == 2) ? b_g : b_o;

    const int tx = tid & 15;   // col group
    const int ty = tid >> 4;   // row group

    ull acc[8][4];             // 8 rows x 4 f32x2 (= 8 cols)
#pragma unroll
    for (int i = 0; i < 8; i++)
#pragma unroll
        for (int j = 0; j < 4; j++) acc[i][j] = 0ull;

    for (int k0 = 0; k0 < DD; k0 += 16) {
#pragma unroll
        for (int l = 0; l < 2; l++) {
            int id  = tid + l * 256;
            int row = id >> 2;
            int kq  = (id & 3) * 4;
            float4 v = *(const float4*)&x[(m0 + row) * (size_t)DD + k0 + kq];
            As[kq + 0][row] = v.x;
            As[kq + 1][row] = v.y;
            As[kq + 2][row] = v.z;
            As[kq + 3][row] = v.w;
        }
#pragma unroll
        for (int l = 0; l < 2; l++) {
            int id = tid + l * 256;
            int kr = id >> 5;
            int nq = (id & 31) * 4;
            *(float4*)&Bs[kr][nq] =
                *(const float4*)&W[(size_t)(k0 + kr) * HH + col0 + nq];
        }
        __syncthreads();

#pragma unroll
        for (int k = 0; k < 16; k++) {
            float a[8];
            *(float4*)&a[0] = *(const float4*)&As[k][ty * 8];
            *(float4*)&a[4] = *(const float4*)&As[k][ty * 8 + 4];
            ull b2[4];
            const ull* bp0 = (const ull*)&Bs[k][tx * 4];
            const ull* bp1 = (const ull*)&Bs[k][64 + tx * 4];
            b2[0] = bp0[0]; b2[1] = bp0[1];
            b2[2] = bp1[0]; b2[3] = bp1[1];
#pragma unroll
            for (int i = 0; i < 8; i++) {
                ull a2 = pack2(a[i], a[i]);
#pragma unroll
                for (int j = 0; j < 4; j++)
                    acc[i][j] = fma2(a2, b2[j], acc[i][j]);
            }
        }
        __syncthreads();
    }

    // Epilogue: + bias, write to g_xp in [t][b][4H] layout
#pragma unroll
    for (int i = 0; i < 8; i++) {
        size_t m = m0 + ty * 8 + i;
        int bb = (int)(m >> 10);      // batch
        int t  = (int)(m & 1023);     // time
        float* __restrict__ xp = (t < 512) ? g_xp0 : g_xp1;
        size_t base = ((size_t)(t & 511) * BB + bb) * NG + n0;
#pragma unroll
        for (int p = 0; p < 4; p++) {
            int c = (p >> 1) * 64 + tx * 4 + (p & 1) * 2;
            float2 v = unpack2(acc[i][p]);
            v.x += bias[col0 + c + 0];
            v.y += bias[col0 + c + 1];
            *(float2*)&xp[base + c] = v;
        }
    }
}

// ---------------------------------------------------------------------------
// Phase 2 (persistent): all 1024 steps in ONE kernel. 128 CTAs; CTA cb owns
// c-cols [cb*8, cb*8+8) (32 gate cols). Software grid barrier between steps.
// ---------------------------------------------------------------------------
__global__ __launch_bounds__(256) void lstm_seq_kernel(
    const float* __restrict__ Whi, const float* __restrict__ Whf,
    const float* __restrict__ Whg, const float* __restrict__ Who)
{
    __shared__ float As[128][36];   // h_in tile [b][k], padded
    __shared__ float Bs[32][32];    // Wh tile [k][gate*8+j]

    const int cb = blockIdx.x;     // 0..127
    const int tid = threadIdx.x;
    const int tx = tid & 15;       // col pair (2 of 32 gate cols)
    const int ty = tid >> 4;       // 8-row group

    for (int t = 0; t < TT; t++) {
        const float* __restrict__ h_in = g_h[t & 1];
        float* __restrict__ h_out = g_h[(t + 1) & 1];
        const float* __restrict__ xp =
            ((t < 512) ? g_xp0 : g_xp1) + (size_t)(t & 511) * BB * NG;

        ull acc[8];                // 8 rows x 1 f32x2 (2 cols)
#pragma unroll
        for (int i = 0; i < 8; i++) acc[i] = 0ull;

        for (int k0 = 0; k0 < HH; k0 += 32) {
            // h tile: 128 b x 32 k
#pragma unroll
            for (int l = 0; l < 4; l++) {
                int id = tid + l * 256;
                int b  = id >> 3;
                int kq = (id & 7) * 4;
                *(float4*)&As[b][kq] =
                    *(const float4*)&h_in[(size_t)b * HH + k0 + kq];
            }
            // Wh tile: 32 k x (4 gates x 8 cols)
            {
                int kr = tid >> 3;
                int slot = tid & 7;
                int g  = slot >> 1;
                int j4 = (slot & 1) * 4;
                const float* __restrict__ W =
                    (g == 0) ? Whi : (g == 1) ? Whf : (g == 2) ? Whg : Who;
                *(float4*)&Bs[kr][g * 8 + j4] =
                    *(const float4*)&W[(size_t)(k0 + kr) * HH + cb * 8 + j4];
            }
            __syncthreads();

#pragma unroll
            for (int k = 0; k < 32; k++) {
                ull bv = *(const ull*)&Bs[k][tx * 2];
#pragma unroll
                for (int i = 0; i < 8; i++) {
                    float a = As[ty * 8 + i][k];
                    acc[i] = fma2(pack2(a, a), bv, acc[i]);
                }
            }
            __syncthreads();
        }

        // Stage gates (+xp) in smem, reuse A tile storage
        float* gs = &As[0][0];
#pragma unroll
        for (int i = 0; i < 8; i++) {
            int b = ty * 8 + i;
            float2 v = unpack2(acc[i]);
            int col = tx * 2;
            int g0 = col >> 3, j0 = col & 7;
            int g1 = (col + 1) >> 3, j1 = (col + 1) & 7;
            gs[b * 32 + col]     = v.x + xp[(size_t)b * NG + g0 * HH + cb * 8 + j0];
            gs[b * 32 + col + 1] = v.y + xp[(size_t)b * NG + g1 * HH + cb * 8 + j1];
        }
        __syncthreads();

#pragma unroll
        for (int r = 0; r < 4; r++) {
            int e = tid + r * 256;     // 0..1023 = 128 b x 8 cols
            int b = e >> 3, jj = e & 7;
            float iv = gs[b * 32 +  0 + jj];
            float fv = gs[b * 32 +  8 + jj];
            float gv = gs[b * 32 + 16 + jj];
            float ov = gs[b * 32 + 24 + jj];
            float si = 1.f / (1.f + expf(-iv));
            float sf = 1.f / (1.f + expf(-fv));
            float tg = tanhf(gv);
            float so = 1.f / (1.f + expf(-ov));
            int cidx = b * HH + cb * 8 + jj;
            float c = sf * g_c[cidx] + si * tg;
            g_c[cidx] = c;
            h_out[cidx] = so * tanhf(c);
        }

        // grid barrier (skip after last step; kernel end syncs)
        if (t < TT - 1) {
            __syncthreads();
            if (tid == 0) {
                __threadfence();
                atomicAdd(&g_bar, 1u);
                unsigned tgt = (unsigned)NCTA * (unsigned)(t + 1);
                while (ld_acq(&g_bar) < tgt) { __nanosleep(32); }
            }
            __syncthreads();
        }
    }
}

// ---------------------------------------------------------------------------
// Output: (h_T, c_T) concatenated. After t=0..1023, final h lives in g_h[0].
// ---------------------------------------------------------------------------
__global__ void final_kernel(float* __restrict__ out) {
    int i = blockIdx.x * blockDim.x + threadIdx.x;
    if (i < BB * HH) {
        out[i] = g_h[0][i];
        out[BB * HH + i] = g_c[i];
    }
}

extern "C" void kernel_launch(void* const* d_in, const int* in_sizes, int n_in,
                              void* d_out, int out_size)
{
    const float* x   = (const float*)d_in[0];
    const float* Wii = (const float*)d_in[1];
    const float* Wif = (const float*)d_in[2];
    const float* Wig = (const float*)d_in[3];
    const float* Wio = (const float*)d_in[4];
    const float* Whi = (const float*)d_in[5];
    const float* Whf = (const float*)d_in[6];
    const float* Whg = (const float*)d_in[7];
    const float* Who = (const float*)d_in[8];
    const float* b_i = (const float*)d_in[9];
    const float* b_f = (const float*)d_in[10];
    const float* b_g = (const float*)d_in[11];
    const float* b_o = (const float*)d_in[12];
    float* out = (float*)d_out;

    init_kernel<<<512, 256>>>();

    dim3 gx(32, 1024);   // N tiles x M tiles
    xproj_kernel<<<gx, 256>>>(x, Wii, Wif, Wig, Wio, b_i, b_f, b_g, b_o);

    lstm_seq_kernel<<<NCTA, 256>>>(Whi, Whf, Whg, Who);

    final_kernel<<<512, 256>>>(out);
}

// round 3
// speedup vs baseline: 1.0012x; 1.0012x over previous
#include <cuda_runtime.h>

#define BB 128
#define TT 1024
#define DD 1024
#define HH 1024
#define NG 4096   // 4*H
#define NCTA 128  // persistent phase-2 CTAs (one wave; 148 SMs)

typedef unsigned long long ull;

// Scratch: x_proj[t][b][4H] fp32, split into two 1 GB halves (t<512 / t>=512)
__device__ float g_xp0[(size_t)512 * BB * NG];
__device__ float g_xp1[(size_t)512 * BB * NG];
__device__ float g_h[2][BB * HH];   // ping-pong hidden state
__device__ float g_c[BB * HH];      // cell state (in-place per element)
__device__ unsigned g_bar;          // monotonic grid-barrier counter

// ---- packed f32x2 helpers (sm_10x dual-lane fp32) -------------------------
__device__ __forceinline__ ull fma2(ull a, ull b, ull c) {
    ull d;
    asm("fma.rn.f32x2 %0, %1, %2, %3;" : "=l"(d) : "l"(a), "l"(b), "l"(c));
    return d;
}
__device__ __forceinline__ ull pack2(float lo, float hi) {
    ull d;
    asm("mov.b64 %0, {%1, %2};" : "=l"(d) : "f"(lo), "f"(hi));
    return d;
}
__device__ __forceinline__ float2 unpack2(ull v) {
    float2 r;
    asm("mov.b64 {%0, %1}, %2;" : "=f"(r.x), "=f"(r.y) : "l"(v));
    return r;
}
__device__ __forceinline__ unsigned ld_acq(const unsigned* p) {
    unsigned v;
    asm volatile("ld.global.acquire.gpu.u32 %0, [%1];" : "=r"(v) : "l"(p));
    return v;
}

// ---------------------------------------------------------------------------
// Zero h0, c0, barrier counter (re-runs every replay -> deterministic)
// ---------------------------------------------------------------------------
__global__ void init_kernel() {
    int i = blockIdx.x * blockDim.x + threadIdx.x;
    if (i < BB * HH) {
        g_h[0][i] = 0.f;
        g_c[i] = 0.f;
    }
    if (i == 0) g_bar = 0u;
}

// ---------------------------------------------------------------------------
// Phase 1: x_proj[t][b][g] = sum_d x[b][t][d] * Wi[d][g] + bias[g]
// A = x viewed as [B*T, D]. C tile 128x128, 256 threads, 8x8 per thread
// (accumulated as 8 x 4 f32x2), BK=16.
// ---------------------------------------------------------------------------
__global__ __launch_bounds__(256) void xproj_kernel(
    const float* __restrict__ x,
    const float* __restrict__ Wii, const float* __restrict__ Wif,
    const float* __restrict__ Wig, const float* __restrict__ Wio,
    const float* __restrict__ b_i, const float* __restrict__ b_f,
    const float* __restrict__ b_g, const float* __restrict__ b_o)
{
    __shared__ float As[16][128];   // As[k][m]
    __shared__ float Bs[16][128];   // Bs[k][n]

    const int tid = threadIdx.x;
    const int n0 = blockIdx.x * 128;            // global gate col base
    const size_t m0 = (size_t)blockIdx.y * 128; // row base over B*T

    const int gate = n0 >> 10;
    const int col0 = n0 & 1023;
    const float* __restrict__ W =
        (gate == 0) ? Wii : (gate == 1) ? Wif : (gate == 2) ? Wig : Wio;
    const float* __restrict__ bias =
        (gate == 0) ? b_i : (gate == 1) ? b_f : (gate == 2) ? b_g : b_o;

    const int tx = tid & 15;   // col group
    const int ty = tid >> 4;   // row group

    ull acc[8][4];             // 8 rows x 4 f32x2 (= 8 cols)
#pragma unroll
    for (int i = 0; i < 8; i++)
#pragma unroll
        for (int j = 0; j < 4; j++) acc[i][j] = 0ull;

    for (int k0 = 0; k0 < DD; k0 += 16) {
#pragma unroll
        for (int l = 0; l < 2; l++) {
            int id  = tid + l * 256;
            int row = id >> 2;
            int kq  = (id & 3) * 4;
            float4 v = *(const float4*)&x[(m0 + row) * (size_t)DD + k0 + kq];
            As[kq + 0][row] = v.x;
            As[kq + 1][row] = v.y;
            As[kq + 2][row] = v.z;
            As[kq + 3][row] = v.w;
        }
#pragma unroll
        for (int l = 0; l < 2; l++) {
            int id = tid + l * 256;
            int kr = id >> 5;
            int nq = (id & 31) * 4;
            *(float4*)&Bs[kr][nq] =
                *(const float4*)&W[(size_t)(k0 + kr) * HH + col0 + nq];
        }
        __syncthreads();

#pragma unroll
        for (int k = 0; k < 16; k++) {
            float a[8];
            *(float4*)&a[0] = *(const float4*)&As[k][ty * 8];
            *(float4*)&a[4] = *(const float4*)&As[k][ty * 8 + 4];
            ull b2[4];
            const ull* bp0 = (const ull*)&Bs[k][tx * 4];
            const ull* bp1 = (const ull*)&Bs[k][64 + tx * 4];
            b2[0] = bp0[0]; b2[1] = bp0[1];
            b2[2] = bp1[0]; b2[3] = bp1[1];
#pragma unroll
            for (int i = 0; i < 8; i++) {
                ull a2 = pack2(a[i], a[i]);
#pragma unroll
                for (int j = 0; j < 4; j++)
                    acc[i][j] = fma2(a2, b2[j], acc[i][j]);
            }
        }
        __syncthreads();
    }

    // Epilogue: + bias, write to g_xp in [t][b][4H] layout
#pragma unroll
    for (int i = 0; i < 8; i++) {
        size_t m = m0 + ty * 8 + i;
        int bb = (int)(m >> 10);      // batch
        int t  = (int)(m & 1023);     // time
        float* __restrict__ xp = (t < 512) ? g_xp0 : g_xp1;
        size_t base = ((size_t)(t & 511) * BB + bb) * NG + n0;
#pragma unroll
        for (int p = 0; p < 4; p++) {
            int c = (p >> 1) * 64 + tx * 4 + (p & 1) * 2;
            float2 v = unpack2(acc[i][p]);
            v.x += bias[col0 + c + 0];
            v.y += bias[col0 + c + 1];
            *(float2*)&xp[base + c] = v;
        }
    }
}

// ---------------------------------------------------------------------------
// Phase 2 (persistent): all 1024 steps in ONE kernel. 128 CTAs; CTA cb owns
// c-cols [cb*8, cb*8+8) (32 gate cols). Software grid barrier between steps.
// ---------------------------------------------------------------------------
__global__ __launch_bounds__(256) void lstm_seq_kernel(
    const float* __restrict__ Whi, const float* __restrict__ Whf,
    const float* __restrict__ Whg, const float* __restrict__ Who)
{
    __shared__ float As[128][36];   // h_in tile [b][k], padded
    __shared__ float Bs[32][32];    // Wh tile [k][gate*8+j]

    const int cb = blockIdx.x;     // 0..127
    const int tid = threadIdx.x;
    const int tx = tid & 15;       // col pair (2 of 32 gate cols)
    const int ty = tid >> 4;       // 8-row group

    for (int t = 0; t < TT; t++) {
        const float* __restrict__ h_in = g_h[t & 1];
        float* __restrict__ h_out = g_h[(t + 1) & 1];
        const float* __restrict__ xp =
            ((t < 512) ? g_xp0 : g_xp1) + (size_t)(t & 511) * BB * NG;

        ull acc[8];                // 8 rows x 1 f32x2 (2 cols)
#pragma unroll
        for (int i = 0; i < 8; i++) acc[i] = 0ull;

        for (int k0 = 0; k0 < HH; k0 += 32) {
            // h tile: 128 b x 32 k
#pragma unroll
            for (int l = 0; l < 4; l++) {
                int id = tid + l * 256;
                int b  = id >> 3;
                int kq = (id & 7) * 4;
                *(float4*)&As[b][kq] =
                    *(const float4*)&h_in[(size_t)b * HH + k0 + kq];
            }
            // Wh tile: 32 k x (4 gates x 8 cols)
            {
                int kr = tid >> 3;
                int slot = tid & 7;
                int g  = slot >> 1;
                int j4 = (slot & 1) * 4;
                const float* __restrict__ W =
                    (g == 0) ? Whi : (g == 1) ? Whf : (g == 2) ? Whg : Who;
                *(float4*)&Bs[kr][g * 8 + j4] =
                    *(const float4*)&W[(size_t)(k0 + kr) * HH + cb * 8 + j4];
            }
            __syncthreads();

#pragma unroll
            for (int k = 0; k < 32; k++) {
                ull bv = *(const ull*)&Bs[k][tx * 2];
#pragma unroll
                for (int i = 0; i < 8; i++) {
                    float a = As[ty * 8 + i][k];
                    acc[i] = fma2(pack2(a, a), bv, acc[i]);
                }
            }
            __syncthreads();
        }

        // Stage gates (+xp) in smem, reuse A tile storage
        float* gs = &As[0][0];
#pragma unroll
        for (int i = 0; i < 8; i++) {
            int b = ty * 8 + i;
            float2 v = unpack2(acc[i]);
            int col = tx * 2;
            int g0 = col >> 3, j0 = col & 7;
            int g1 = (col + 1) >> 3, j1 = (col + 1) & 7;
            gs[b * 32 + col]     = v.x + xp[(size_t)b * NG + g0 * HH + cb * 8 + j0];
            gs[b * 32 + col + 1] = v.y + xp[(size_t)b * NG + g1 * HH + cb * 8 + j1];
        }
        __syncthreads();

#pragma unroll
        for (int r = 0; r < 4; r++) {
            int e = tid + r * 256;     // 0..1023 = 128 b x 8 cols
            int b = e >> 3, jj = e & 7;
            float iv = gs[b * 32 +  0 + jj];
            float fv = gs[b * 32 +  8 + jj];
            float gv = gs[b * 32 + 16 + jj];
            float ov = gs[b * 32 + 24 + jj];
            float si = 1.f / (1.f + expf(-iv));
            float sf = 1.f / (1.f + expf(-fv));
            float tg = tanhf(gv);
            float so = 1.f / (1.f + expf(-ov));
            int cidx = b * HH + cb * 8 + jj;
            float c = sf * g_c[cidx] + si * tg;
            g_c[cidx] = c;
            h_out[cidx] = so * tanhf(c);
        }

        // grid barrier (skip after last step; kernel end syncs)
        if (t < TT - 1) {
            __syncthreads();
            if (tid == 0) {
                __threadfence();
                atomicAdd(&g_bar, 1u);
                unsigned tgt = (unsigned)NCTA * (unsigned)(t + 1);
                while (ld_acq(&g_bar) < tgt) { __nanosleep(32); }
            }
            __syncthreads();
        }
    }
}

// ---------------------------------------------------------------------------
// Output: (h_T, c_T) concatenated. After t=0..1023, final h lives in g_h[0].
// ---------------------------------------------------------------------------
__global__ void final_kernel(float* __restrict__ out) {
    int i = blockIdx.x * blockDim.x + threadIdx.x;
    if (i < BB * HH) {
        out[i] = g_h[0][i];
        out[BB * HH + i] = g_c[i];
    }
}

extern "C" void kernel_launch(void* const* d_in, const int* in_sizes, int n_in,
                              void* d_out, int out_size)
{
    const float* x   = (const float*)d_in[0];
    const float* Wii = (const float*)d_in[1];
    const float* Wif = (const float*)d_in[2];
    const float* Wig = (const float*)d_in[3];
    const float* Wio = (const float*)d_in[4];
    const float* Whi = (const float*)d_in[5];
    const float* Whf = (const float*)d_in[6];
    const float* Whg = (const float*)d_in[7];
    const float* Who = (const float*)d_in[8];
    const float* b_i = (const float*)d_in[9];
    const float* b_f = (const float*)d_in[10];
    const float* b_g = (const float*)d_in[11];
    const float* b_o = (const float*)d_in[12];
    float* out = (float*)d_out;

    init_kernel<<<512, 256>>>();

    dim3 gx(32, 1024);   // N tiles x M tiles
    xproj_kernel<<<gx, 256>>>(x, Wii, Wif, Wig, Wio, b_i, b_f, b_g, b_o);

    lstm_seq_kernel<<<NCTA, 256>>>(Whi, Whf, Whg, Who);

    final_kernel<<<512, 256>>>(out);
}

// round 6
// speedup vs baseline: 3.8291x; 3.8245x over previous
#include <cuda_runtime.h>
#include <cuda_bf16.h>

typedef unsigned int u32;
typedef unsigned long long u64;
typedef unsigned short u16;

#define TT 1024

// ---- device scratch --------------------------------------------------------
__device__ __align__(1024) float g_xp0[(size_t)512 * 128 * 4096];
__device__ __align__(1024) float g_xp1[(size_t)512 * 128 * 4096];
__device__ __align__(1024) __nv_bfloat16 g_xh[(size_t)128 * 1024 * 1024];
__device__ __align__(1024) __nv_bfloat16 g_xl[(size_t)128 * 1024 * 1024];
__device__ __align__(1024) __nv_bfloat16 g_wih[(size_t)4096 * 1024];
__device__ __align__(1024) __nv_bfloat16 g_wil[(size_t)4096 * 1024];
__device__ __align__(1024) __nv_bfloat16 g_whh[(size_t)4096 * 1024];
__device__ __align__(1024) __nv_bfloat16 g_whl[(size_t)4096 * 1024];
__device__ __align__(1024) __nv_bfloat16 g_hh[2][16 * 128 * 64];
__device__ __align__(1024) __nv_bfloat16 g_hl[2][16 * 128 * 64];
__device__ unsigned g_bar;

// ---- PTX helpers (base sm_103 safe) ---------------------------------------
__device__ __forceinline__ u32 sptr(const void* p) {
    u32 a;
    asm("{ .reg .u64 t; cvta.to.shared.u64 t, %1; cvt.u32.u64 %0, t; }" : "=r"(a) : "l"(p));
    return a;
}
__device__ __forceinline__ void mbar_init(u32 m, u32 cnt) {
    asm volatile("mbarrier.init.shared.b64 [%0], %1;" :: "r"(m), "r"(cnt) : "memory");
}
__device__ __forceinline__ void mbar_expect_tx(u32 m, u32 bytes) {
    asm volatile("mbarrier.arrive.expect_tx.shared.b64 _, [%0], %1;" :: "r"(m), "r"(bytes) : "memory");
}
__device__ __forceinline__ void mbar_arrive(u32 m) {
    asm volatile("mbarrier.arrive.shared.b64 _, [%0];" :: "r"(m) : "memory");
}
__device__ __forceinline__ void mwait(u32 m, u32 parity) {
    asm volatile(
        "{\n\t.reg .pred P;\n"
        "W%=:\n\tmbarrier.try_wait.parity.acquire.cta.shared::cta.b64 P, [%0], %1, 0x989680;\n"
        "\t@P bra D%=;\n\tbra W%=;\nD%=:\n\t}" :: "r"(m), "r"(parity) : "memory");
}
__device__ __forceinline__ void bulk_g2s(u32 dst, const void* src, u32 bytes, u32 m) {
    asm volatile(
        "cp.async.bulk.shared::cluster.global.mbarrier::complete_tx::bytes [%0], [%1], %2, [%3];"
        :: "r"(dst), "l"((u64)__cvta_generic_to_global(src)), "r"(bytes), "r"(m) : "memory");
}
__device__ __forceinline__ void f_proxy() { asm volatile("fence.proxy.async;" ::: "memory"); }
__device__ __forceinline__ unsigned ld_acq(const unsigned* p) {
    unsigned v;
    asm volatile("ld.global.acquire.gpu.u32 %0, [%1];" : "=r"(v) : "l"(p));
    return v;
}
__device__ __forceinline__ void ldsm_x4(u32 (&r)[4], u32 addr) {
    asm volatile("ldmatrix.sync.aligned.m8n8.x4.shared.b16 {%0,%1,%2,%3}, [%4];"
                 : "=r"(r[0]), "=r"(r[1]), "=r"(r[2]), "=r"(r[3]) : "r"(addr));
}
__device__ __forceinline__ void mma16816(float (&d)[4], const u32 (&a)[4], const u32* b) {
    asm volatile(
        "mma.sync.aligned.m16n8k16.row.col.f32.bf16.bf16.f32 "
        "{%0,%1,%2,%3}, {%4,%5,%6,%7}, {%8,%9}, {%0,%1,%2,%3};"
        : "+f"(d[0]), "+f"(d[1]), "+f"(d[2]), "+f"(d[3])
        : "r"(a[0]), "r"(a[1]), "r"(a[2]), "r"(a[3]), "r"(b[0]), "r"(b[1]));
}
__device__ __forceinline__ void split_bf16(float v, u16& h, u16& l) {
    __nv_bfloat16 hb = __float2bfloat16_rn(v);
    __nv_bfloat16 lb = __float2bfloat16_rn(v - __bfloat162float(hb));
    h = *(u16*)&hb; l = *(u16*)&lb;
}

// ---- init ------------------------------------------------------------------
__global__ void init_kernel() {
    int i = blockIdx.x * blockDim.x + threadIdx.x;   // 65536
    ((u32*)g_hh[0])[i] = 0u;
    ((u32*)g_hl[0])[i] = 0u;
    if (i == 0) g_bar = 0u;
}

// ---- conversions to blocked swizzled images --------------------------------
// A-image: [mt][kc(16)][128 rows x 64 k], row=128B, 16B-unit u -> u^(row&7)
__global__ void conv_x_kernel(const float* __restrict__ x) {
    size_t idx = (size_t)blockIdx.x * 256 + threadIdx.x;   // 16,777,216
    u32 m = (u32)(idx >> 7), ku = (u32)(idx & 127);
    const float4* src = (const float4*)(x + (size_t)m * 1024 + ku * 8);
    float4 a = src[0], b = src[1];
    float v[8] = {a.x, a.y, a.z, a.w, b.x, b.y, b.z, b.w};
    union { u16 s[8]; uint4 q; } H, L;
#pragma unroll
    for (int i = 0; i < 8; i++) split_bf16(v[i], H.s[i], L.s[i]);
    u32 mt = m >> 7, r = m & 127, kc = ku >> 3, uu = ku & 7;
    size_t off = ((size_t)(mt * 16 + kc) << 13) + (r << 6) + ((uu ^ (r & 7)) << 3);
    *(uint4*)(g_xh + off) = H.q;
    *(uint4*)(g_xl + off) = L.q;
}
// Wi B-image: [nt(32)][kc(16)][128 n x 64 k]
__global__ void conv_wi_kernel(const float* __restrict__ W0, const float* __restrict__ W1,
                               const float* __restrict__ W2, const float* __restrict__ W3) {
    u32 idx = blockIdx.x * 256 + threadIdx.x;   // 524288
    u32 n = idx & 4095, ku = idx >> 12;
    const float* __restrict__ W = (n < 1024) ? W0 : (n < 2048) ? W1 : (n < 3072) ? W2 : W3;
    u32 col = n & 1023;
    union { u16 s[8]; uint4 q; } H, L;
#pragma unroll
    for (int i = 0; i < 8; i++)
        split_bf16(W[(size_t)(ku * 8 + i) * 1024 + col], H.s[i], L.s[i]);
    u32 nt = n >> 7, r = n & 127, kc = ku >> 3, uu = ku & 7;
    size_t off = ((size_t)(nt * 16 + kc) << 13) + (r << 6) + ((uu ^ (r & 7)) << 3);
    *(uint4*)(g_wih + off) = H.q;
    *(uint4*)(g_wil + off) = L.q;
}
// Wh B-image: [cb(128)][32 rows(j=g*8+(n&7)) x 1024 k], row=2048B, unit ku^(j&7)
__global__ void conv_wh_kernel(const float* __restrict__ W0, const float* __restrict__ W1,
                               const float* __restrict__ W2, const float* __restrict__ W3) {
    u32 idx = blockIdx.x * 256 + threadIdx.x;   // 524288
    u32 n = idx & 1023, ku = (idx >> 10) & 127, g = idx >> 17;
    const float* __restrict__ W = (g == 0) ? W0 : (g == 1) ? W1 : (g == 2) ? W2 : W3;
    union { u16 s[8]; uint4 q; } H, L;
#pragma unroll
    for (int i = 0; i < 8; i++)
        split_bf16(W[(size_t)(ku * 8 + i) * 1024 + n], H.s[i], L.s[i]);
    u32 cb = n >> 3, j = g * 8 + (n & 7);
    size_t off = ((size_t)cb << 15) + (j << 10) + ((ku ^ (j & 7)) << 3);
    *(uint4*)(g_whh + off) = H.q;
    *(uint4*)(g_whl + off) = L.q;
}

// ---- Phase 1: x_proj = x @ Wi + bias. CTA 128x128xK1024, 8 warps ----------
__global__ void __launch_bounds__(256, 1) xproj_mma(
    const float* __restrict__ b_i, const float* __restrict__ b_f,
    const float* __restrict__ b_g, const float* __restrict__ b_o)
{
    extern __shared__ __align__(1024) char smem[];
    const u32 sb = sptr(smem);
    const int tid = threadIdx.x, lane = tid & 31, w = tid >> 5;
    const int bx = blockIdx.x, by = blockIdx.y;
    const u32 SA = sb + 1024, SBB = sb + 66560;

    if (tid == 0) {
        mbar_init(sb + 0, 1);   mbar_init(sb + 8, 1);     // full
        mbar_init(sb + 16, 256); mbar_init(sb + 24, 256); // empty
    }
    __syncthreads();

    const char* axh = (const char*)g_xh + (size_t)by * 262144;
    const char* axl = (const char*)g_xl + (size_t)by * 262144;
    const char* bwh = (const char*)g_wih + (size_t)bx * 262144;
    const char* bwl = (const char*)g_wil + (size_t)bx * 262144;

    auto issue = [&](int c) {
        int buf = c & 1;
        mwait(sb + 16 + buf * 8, ((c >> 1) & 1) ^ 1);
        mbar_expect_tx(sb + buf * 8, 65536);
        bulk_g2s(SA + buf * 32768,           axh + (size_t)c * 16384, 16384, sb + buf * 8);
        bulk_g2s(SA + buf * 32768 + 16384,   axl + (size_t)c * 16384, 16384, sb + buf * 8);
        bulk_g2s(SBB + buf * 32768,          bwh + (size_t)c * 16384, 16384, sb + buf * 8);
        bulk_g2s(SBB + buf * 32768 + 16384,  bwl + (size_t)c * 16384, 16384, sb + buf * 8);
    };
    if (tid == 0) { issue(0); issue(1); }

    const int wr = w >> 2, wc = w & 3;
    const int arow = (lane & 7) + ((lane >> 3) & 1) * 8;
    const int aub  = lane >> 4;
    const int brow = (lane & 7) + (lane >> 4) * 8;
    const int bub  = (lane >> 3) & 1;

    float acc[4][4][4];
#pragma unroll
    for (int i = 0; i < 4; i++)
#pragma unroll
        for (int j = 0; j < 4; j++)
#pragma unroll
            for (int q = 0; q < 4; q++) acc[i][j][q] = 0.f;

    for (int c = 0; c < 16; c++) {
        int buf = c & 1;
        mwait(sb + buf * 8, (c >> 1) & 1);
        u32 Ah = SA + buf * 32768, Al = Ah + 16384;
        u32 Bh = SBB + buf * 32768, Bl = Bh + 16384;
#pragma unroll
        for (int s = 0; s < 4; s++) {
            u32 ah[4][4], al[4][4];
#pragma unroll
            for (int mt = 0; mt < 4; mt++) {
                int r = wr * 64 + mt * 16 + arow;
                u32 off = (u32)(r * 128 + (((s * 2 + aub) ^ (r & 7)) << 4));
                ldsm_x4(ah[mt], Ah + off);
                ldsm_x4(al[mt], Al + off);
            }
#pragma unroll
            for (int np = 0; np < 2; np++) {
                int n = wc * 32 + np * 16 + brow;
                u32 off = (u32)(n * 128 + (((s * 2 + bub) ^ (n & 7)) << 4));
                u32 bh[4], bl[4];
                ldsm_x4(bh, Bh + off);
                ldsm_x4(bl, Bl + off);
#pragma unroll
                for (int mt = 0; mt < 4; mt++) {
                    mma16816(acc[mt][np * 2 + 0], ah[mt], bh + 0);
                    mma16816(acc[mt][np * 2 + 0], ah[mt], bl + 0);
                    mma16816(acc[mt][np * 2 + 0], al[mt], bh + 0);
                    mma16816(acc[mt][np * 2 + 1], ah[mt], bh + 2);
                    mma16816(acc[mt][np * 2 + 1], ah[mt], bl + 2);
                    mma16816(acc[mt][np * 2 + 1], al[mt], bh + 2);
                }
            }
        }
        mbar_arrive(sb + 16 + buf * 8);
        if (tid == 0 && c < 14) issue(c + 2);
    }

    const int gate = bx >> 3;
    const float* __restrict__ bias =
        (gate == 0) ? b_i : (gate == 1) ? b_f : (gate == 2) ? b_g : b_o;
    const int bcol0 = (bx & 7) * 128 + wc * 32 + (lane & 3) * 2;
    float2 bv[4];
#pragma unroll
    for (int nt = 0; nt < 4; nt++)
        bv[nt] = make_float2(bias[bcol0 + nt * 8], bias[bcol0 + nt * 8 + 1]);

    const int colg = bx * 128 + wc * 32 + (lane & 3) * 2;
#pragma unroll
    for (int mt = 0; mt < 4; mt++) {
#pragma unroll
        for (int h2 = 0; h2 < 2; h2++) {
            int m = by * 128 + wr * 64 + mt * 16 + (lane >> 2) + h2 * 8;
            int bb = m >> 10, t = m & 1023;
            float* __restrict__ xp =
                ((t < 512) ? g_xp0 : g_xp1) + ((size_t)(t & 511) * 128 + bb) * 4096 + colg;
#pragma unroll
            for (int nt = 0; nt < 4; nt++) {
                float2 o = make_float2(acc[mt][nt][h2 * 2 + 0] + bv[nt].x,
                                       acc[mt][nt][h2 * 2 + 1] + bv[nt].y);
                *(float2*)(xp + nt * 8) = o;
            }
        }
    }
}

// ---- Phase 2 (persistent): 128 CTAs x 256 thr; Wh slice resident in SMEM ---
__global__ void __launch_bounds__(256, 1) lstm_mma(float* __restrict__ out)
{
    extern __shared__ __align__(1024) char smem[];
    const u32 sb = sptr(smem);
    const int tid = threadIdx.x, lane = tid & 31, w = tid >> 5;
    const int cb = blockIdx.x;
    const u32 SBH = sb + 1024, SBL = sb + 66560, SA = sb + 132096;

    if (tid == 0) {
        mbar_init(sb + 0, 1);   mbar_init(sb + 8, 1);     // full
        mbar_init(sb + 16, 256); mbar_init(sb + 24, 256); // empty
        mbar_init(sb + 32, 1);                            // Wh
        mbar_expect_tx(sb + 32, 131072);
        bulk_g2s(SBH, (const char*)g_whh + (size_t)cb * 65536, 65536, sb + 32);
        bulk_g2s(SBL, (const char*)g_whl + (size_t)cb * 65536, 65536, sb + 32);
    }
    __syncthreads();
    mwait(sb + 32, 0);

    const int arow = (lane & 7) + ((lane >> 3) & 1) * 8;
    const int aub  = lane >> 4;
    const int brow = (lane & 7) + (lane >> 4) * 8;
    const int bub  = (lane >> 3) & 1;
    const int r0 = w * 16 + (lane >> 2), p = lane & 3;
    const u32 aoff_base = (u32)((w * 16 + arow) * 128);
    const int ar7 = (w * 16 + arow) & 7;

    auto issue = [&](int t, int c) {
        int buf = c & 1;
        mwait(sb + 16 + buf * 8, ((c >> 1) & 1) ^ 1);
        mbar_expect_tx(sb + buf * 8, 32768);
        const char* hh = (const char*)g_hh[t & 1] + (size_t)c * 16384;
        const char* hl = (const char*)g_hl[t & 1] + (size_t)c * 16384;
        bulk_g2s(SA + buf * 32768,          hh, 16384, sb + buf * 8);
        bulk_g2s(SA + buf * 32768 + 16384,  hl, 16384, sb + buf * 8);
    };

    float cst[2][2] = {{0.f, 0.f}, {0.f, 0.f}};

    for (int t = 0; t < TT; t++) {
        if (tid == 0) { f_proxy(); issue(t, 0); issue(t, 1); }

        float acc[4][4];
#pragma unroll
        for (int i = 0; i < 4; i++)
#pragma unroll
            for (int q = 0; q < 4; q++) acc[i][q] = 0.f;

        for (int c = 0; c < 16; c++) {
            int buf = c & 1;
            mwait(sb + buf * 8, (c >> 1) & 1);
            u32 Ah = SA + buf * 32768, Al = Ah + 16384;
#pragma unroll
            for (int s = 0; s < 4; s++) {
                u32 ah[4], al[4];
                u32 aoff = aoff_base + (((s * 2 + aub) ^ ar7) << 4);
                ldsm_x4(ah, Ah + aoff);
                ldsm_x4(al, Al + aoff);
                int kk2 = (c * 4 + s) * 2 + bub;
#pragma unroll
                for (int np = 0; np < 2; np++) {
                    int j = np * 16 + brow;
                    u32 boff = (u32)(j * 2048 + ((kk2 ^ (j & 7)) << 4));
                    u32 bh[4], bl[4];
                    ldsm_x4(bh, SBH + boff);
                    ldsm_x4(bl, SBL + boff);
                    mma16816(acc[np * 2 + 0], ah, bh + 0);
                    mma16816(acc[np * 2 + 0], ah, bl + 0);
                    mma16816(acc[np * 2 + 0], al, bh + 0);
                    mma16816(acc[np * 2 + 1], ah, bh + 2);
                    mma16816(acc[np * 2 + 1], ah, bl + 2);
                    mma16816(acc[np * 2 + 1], al, bh + 2);
                }
            }
            mbar_arrive(sb + 16 + buf * 8);
            if (tid == 0 && c < 14) issue(t, c + 2);
        }

        // epilogue: acc[0..3] = gates i,f,g,o at cols jj=2p,2p+1; rows r0, r0+8
        const float* xpb = ((t < 512) ? g_xp0 : g_xp1) + (size_t)(t & 511) * 524288;
        float hv[2][2];
#pragma unroll
        for (int half = 0; half < 2; half++) {
            int b = r0 + half * 8;
            const float* xr = xpb + (size_t)b * 4096 + cb * 8 + p * 2;
            float2 xi = *(const float2*)(xr);
            float2 xf = *(const float2*)(xr + 1024);
            float2 xg = *(const float2*)(xr + 2048);
            float2 xo = *(const float2*)(xr + 3072);
#pragma unroll
            for (int q = 0; q < 2; q++) {
                float iv = acc[0][half * 2 + q] + (q ? xi.y : xi.x);
                float fv = acc[1][half * 2 + q] + (q ? xf.y : xf.x);
                float gv = acc[2][half * 2 + q] + (q ? xg.y : xg.x);
                float ov = acc[3][half * 2 + q] + (q ? xo.y : xo.x);
                float si = 1.f / (1.f + expf(-iv));
                float sf = 1.f / (1.f + expf(-fv));
                float tg = tanhf(gv);
                float so = 1.f / (1.f + expf(-ov));
                cst[half][q] = sf * cst[half][q] + si * tg;
                hv[half][q] = so * tanhf(cst[half][q]);
            }
            u16 h0, l0, h1, l1;
            split_bf16(hv[half][0], h0, l0);
            split_bf16(hv[half][1], h1, l1);
            u32 hw = (u32)h0 | ((u32)h1 << 16);
            u32 lw = (u32)l0 | ((u32)l1 << 16);
            u32 off = (u32)(cb >> 3) * 16384 + (u32)b * 128
                    + (u32)(((cb & 7) ^ (b & 7)) << 4) + (u32)p * 4;
            *(u32*)((char*)g_hh[(t + 1) & 1] + off) = hw;
            *(u32*)((char*)g_hl[(t + 1) & 1] + off) = lw;
        }

        if (t == TT - 1) {
#pragma unroll
            for (int half = 0; half < 2; half++) {
                int b = r0 + half * 8;
                float* o1 = out + (size_t)b * 1024 + cb * 8 + p * 2;
                o1[0] = hv[half][0]; o1[1] = hv[half][1];
                float* o2 = o1 + 131072;
                o2[0] = cst[half][0]; o2[1] = cst[half][1];
            }
        }

        if (t < TT - 1) {
            __syncthreads();
            if (tid == 0) {
                __threadfence();
                atomicAdd(&g_bar, 1u);
                unsigned tgt = 128u * (unsigned)(t + 1);
                while (ld_acq(&g_bar) < tgt) __nanosleep(64);
            }
            __syncthreads();
        }
    }
}

// ---------------------------------------------------------------------------
extern "C" void kernel_launch(void* const* d_in, const int* in_sizes, int n_in,
                              void* d_out, int out_size)
{
    const float* x   = (const float*)d_in[0];
    const float* Wii = (const float*)d_in[1];
    const float* Wif = (const float*)d_in[2];
    const float* Wig = (const float*)d_in[3];
    const float* Wio = (const float*)d_in[4];
    const float* Whi = (const float*)d_in[5];
    const float* Whf = (const float*)d_in[6];
    const float* Whg = (const float*)d_in[7];
    const float* Who = (const float*)d_in[8];
    const float* b_i = (const float*)d_in[9];
    const float* b_f = (const float*)d_in[10];
    const float* b_g = (const float*)d_in[11];
    const float* b_o = (const float*)d_in[12];
    float* out = (float*)d_out;

    cudaFuncSetAttribute(xproj_mma, cudaFuncAttributeMaxDynamicSharedMemorySize, 132096);
    cudaFuncSetAttribute(lstm_mma,  cudaFuncAttributeMaxDynamicSharedMemorySize, 197632);

    init_kernel<<<256, 256>>>();
    conv_x_kernel<<<65536, 256>>>(x);
    conv_wi_kernel<<<2048, 256>>>(Wii, Wif, Wig, Wio);
    conv_wh_kernel<<<2048, 256>>>(Whi, Whf, Whg, Who);

    dim3 g1(32, 1024);
    xproj_mma<<<g1, 256, 132096>>>(b_i, b_f, b_g, b_o);
    lstm_mma<<<128, 256, 197632>>>(out);
}